// round 7
// baseline (speedup 1.0000x reference)
#include <cuda_runtime.h>

// Problem constants
#define Tn 336
#define Fn 12
#define Hn 50
#define Bn 4096
#define BC 32          // batch rows per CTA
#define NTHREADS 512
#define HPAD 52        // h row stride (16B-multiple)
#define RPG 4          // rows per group (8 groups x 2 warps)

// shared memory float offsets
// weight arrays store j-PAIRS per gate, split A (gates i,f) / B (gates g,o):
//   A[(p*50+u)*4 + {i_j0,i_j1,f_j0,f_j1}]   (16B per (p,u), conflict-free in u)
#define W0XA_OFF 0        // layer0 x-part  A: 6 pairs  -> 1200
#define W0XB_OFF 1200     // layer0 x-part  B: 1200
#define W0HA_OFF 2400     // layer0 h-part  A: 25 pairs -> 5000
#define W0HB_OFF 7400     // 5000
#define W1IA_OFF 12400    // layer1 input(h0) A
#define W1IB_OFF 17400
#define W1RA_OFF 22400    // layer1 recurrent(h1) A
#define W1RB_OFF 27400
#define W2IA_OFF 32400
#define W2IB_OFF 37400
#define W2RA_OFF 42400
#define W2RB_OFF 47400
#define HS_OFF   52400    // h state  3 * 32 * 52 = 4992
#define XS_OFF   57392    // x tile   32 * 12 = 384
#define SMEM_FLOATS 57776
#define SMEM_BYTES (SMEM_FLOATS * 4)

typedef unsigned long long u64;

// packed dual-fp32 FMA (sm_103a FFMA2): z += w * h (elementwise, 2 fp32 lanes)
__device__ __forceinline__ void ffma2(u64& z, const u64 w, const u64 h) {
    asm("fma.rn.f32x2 %0, %1, %2, %0;" : "+l"(z) : "l"(w), "l"(h));
}
__device__ __forceinline__ void unpack2(const u64 v, float& lo, float& hi) {
    asm("mov.b64 {%0, %1}, %2;" : "=f"(lo), "=f"(hi) : "l"(v));
}

__device__ __forceinline__ float sigmoidf_(float v) {
    return 1.0f / (1.0f + __expf(-v));
}
// precise-enough tanh: 1 - 2/(1+e^{2x}); ~1e-7 rel err
__device__ __forceinline__ float tanhf_(float v) {
    const float e = __expf(2.0f * v);
    return 1.0f - 2.0f / (e + 1.0f);
}

// named barrier for a 2-warp group (ids 1..8; 0 reserved for __syncthreads)
__device__ __forceinline__ void barg(int id) {
    asm volatile("bar.sync %0, 64;" :: "r"(id) : "memory");
}

// 25 j-pairs over a 50-long vector (stride HPAD), j-pair-packed FFMA2.
__device__ __forceinline__ void acc25(u64 zi[RPG], u64 zf[RPG], u64 zg[RPG], u64 zo[RPG],
                                      const float* __restrict__ WA,
                                      const float* __restrict__ WB,
                                      const float* __restrict__ hb, int u)
{
#pragma unroll 1
    for (int p = 0; p < 24; p += 2) {
        const ulonglong2 wa0 = *(const ulonglong2*)(WA + ((p+0)*50 + u)*4);
        const ulonglong2 wb0 = *(const ulonglong2*)(WB + ((p+0)*50 + u)*4);
        const ulonglong2 wa1 = *(const ulonglong2*)(WA + ((p+1)*50 + u)*4);
        const ulonglong2 wb1 = *(const ulonglong2*)(WB + ((p+1)*50 + u)*4);
#pragma unroll
        for (int r = 0; r < RPG; r++) {
            const ulonglong2 hv = *(const ulonglong2*)(hb + r*HPAD + 2*p);
            ffma2(zi[r], wa0.x, hv.x); ffma2(zf[r], wa0.y, hv.x);
            ffma2(zg[r], wb0.x, hv.x); ffma2(zo[r], wb0.y, hv.x);
            ffma2(zi[r], wa1.x, hv.y); ffma2(zf[r], wa1.y, hv.y);
            ffma2(zg[r], wb1.x, hv.y); ffma2(zo[r], wb1.y, hv.y);
        }
    }
    // remainder pair p=24 (j=48,49)
    const ulonglong2 wa = *(const ulonglong2*)(WA + (24*50 + u)*4);
    const ulonglong2 wb = *(const ulonglong2*)(WB + (24*50 + u)*4);
#pragma unroll
    for (int r = 0; r < RPG; r++) {
        const u64 hp = *(const u64*)(hb + r*HPAD + 48);
        ffma2(zi[r], wa.x, hp); ffma2(zf[r], wa.y, hp);
        ffma2(zg[r], wb.x, hp); ffma2(zo[r], wb.y, hp);
    }
}

// 6 j-pairs over the 12-long x vector (stride Fn)
__device__ __forceinline__ void accX(u64 zi[RPG], u64 zf[RPG], u64 zg[RPG], u64 zo[RPG],
                                     const float* __restrict__ WA,
                                     const float* __restrict__ WB,
                                     const float* __restrict__ xr, int u)
{
#pragma unroll
    for (int p = 0; p < 6; p += 2) {
        const ulonglong2 wa0 = *(const ulonglong2*)(WA + ((p+0)*50 + u)*4);
        const ulonglong2 wb0 = *(const ulonglong2*)(WB + ((p+0)*50 + u)*4);
        const ulonglong2 wa1 = *(const ulonglong2*)(WA + ((p+1)*50 + u)*4);
        const ulonglong2 wb1 = *(const ulonglong2*)(WB + ((p+1)*50 + u)*4);
#pragma unroll
        for (int r = 0; r < RPG; r++) {
            const ulonglong2 hv = *(const ulonglong2*)(xr + r*Fn + 2*p);
            ffma2(zi[r], wa0.x, hv.x); ffma2(zf[r], wa0.y, hv.x);
            ffma2(zg[r], wb0.x, hv.x); ffma2(zo[r], wb0.y, hv.x);
            ffma2(zi[r], wa1.x, hv.y); ffma2(zf[r], wa1.y, hv.y);
            ffma2(zg[r], wb1.x, hv.y); ffma2(zo[r], wb1.y, hv.y);
        }
    }
}

__global__ void __launch_bounds__(NTHREADS, 1)
lstm_fused(const float* __restrict__ x,
           const float* __restrict__ Wih0, const float* __restrict__ Whh0,
           const float* __restrict__ bih0, const float* __restrict__ bhh0,
           const float* __restrict__ Wih1, const float* __restrict__ Whh1,
           const float* __restrict__ bih1, const float* __restrict__ bhh1,
           const float* __restrict__ Wih2, const float* __restrict__ Whh2,
           const float* __restrict__ bih2, const float* __restrict__ bhh2,
           const float* __restrict__ Wlin, const float* __restrict__ blin,
           float* __restrict__ out)
{
    extern __shared__ float sm[];
    float* HS = sm + HS_OFF;   // [3][BC][HPAD]
    float* XS = sm + XS_OFF;   // [BC][12]

    const int tid   = threadIdx.x;
    const int lane  = tid & 31;
    const int wid   = tid >> 5;
    const int grp   = wid >> 1;               // 0..7
    const int bid   = grp + 1;                // named barrier id
    const int r0    = grp * RPG;              // row base (4 rows)
    const int u     = (wid & 1) * 32 + lane;  // unit id
    const bool act  = (u < Hn);
    const int gtid  = tid & 63;               // thread id within group

    // ---- stage weights: j-pair layout, A = gates(i,f), B = gates(g,o) ----
    // layer0 x-part: 6 pairs from Wih0 [4H x 12]
    for (int idx = tid; idx < 1200; idx += NTHREADS) {
        const int uu = (idx >> 2) % 50;
        const int p  = idx / 200;
        const int jj = idx & 1;
        const int gh = (idx >> 1) & 1;
        const int j  = 2*p + jj;
        sm[W0XA_OFF + idx] = Wih0[((0 + gh)*50 + uu)*12 + j];
        sm[W0XB_OFF + idx] = Wih0[((2 + gh)*50 + uu)*12 + j];
    }
    // 25-pair blocks from [4H x 50] sources
    {
        const float* srcs[5] = { Whh0, Wih1, Whh1, Wih2, Whh2 };
        const int offA[5] = { W0HA_OFF, W1IA_OFF, W1RA_OFF, W2IA_OFF, W2RA_OFF };
        const int offB[5] = { W0HB_OFF, W1IB_OFF, W1RB_OFF, W2IB_OFF, W2RB_OFF };
#pragma unroll 1
        for (int s = 0; s < 5; s++) {
            const float* Wsrc = srcs[s];
            float* A = sm + offA[s];
            float* B = sm + offB[s];
            for (int idx = tid; idx < 5000; idx += NTHREADS) {
                const int uu = (idx >> 2) % 50;
                const int p  = idx / 200;
                const int jj = idx & 1;
                const int gh = (idx >> 1) & 1;
                const int j  = 2*p + jj;
                A[idx] = Wsrc[((0 + gh)*50 + uu)*50 + j];
                B[idx] = Wsrc[((2 + gh)*50 + uu)*50 + j];
            }
        }
    }
    for (int idx = tid; idx < 3*BC*HPAD; idx += NTHREADS) HS[idx] = 0.0f;

    // biases as plain floats (added in the horizontal reduction)
    float bi0=0.f,bf0=0.f,bg0=0.f,bo0=0.f;
    float bi1=0.f,bf1=0.f,bg1=0.f,bo1=0.f;
    float bi2=0.f,bf2=0.f,bg2=0.f,bo2=0.f;
    if (act) {
        bi0 = bih0[u]       + bhh0[u];
        bf0 = bih0[50 + u]  + bhh0[50 + u];
        bg0 = bih0[100 + u] + bhh0[100 + u];
        bo0 = bih0[150 + u] + bhh0[150 + u];
        bi1 = bih1[u]       + bhh1[u];
        bf1 = bih1[50 + u]  + bhh1[50 + u];
        bg1 = bih1[100 + u] + bhh1[100 + u];
        bo1 = bih1[150 + u] + bhh1[150 + u];
        bi2 = bih2[u]       + bhh2[u];
        bf2 = bih2[50 + u]  + bhh2[50 + u];
        bg2 = bih2[100 + u] + bhh2[100 + u];
        bo2 = bih2[150 + u] + bhh2[150 + u];
    }

    float c0[RPG], c1[RPG], c2[RPG];
#pragma unroll
    for (int r = 0; r < RPG; r++) { c0[r] = 0.f; c1[r] = 0.f; c2[r] = 0.f; }

    const long long bbase = (long long)blockIdx.x * BC;
    const float* xb = x + bbase * (Tn * Fn);

    const int xrow = r0 + gtid / Fn;          // valid if gtid < 48
    const int xcol = gtid % Fn;

    __syncthreads();

    float* HS0 = HS + 0*(BC*HPAD) + r0*HPAD;
    float* HS1 = HS + 1*(BC*HPAD) + r0*HPAD;
    float* HS2 = HS + 2*(BC*HPAD) + r0*HPAD;
    float* XSg = XS + r0*Fn;

    for (int t = 0; t < Tn; t++) {
        // ---- group-local x tile load: 4 rows x 12 ----
        if (gtid < RPG*Fn)
            XSg[gtid] = xb[xrow*(Tn*Fn) + t*Fn + xcol];
        barg(bid);

        float hn[RPG];

        // ================= layer 0 =================
        if (act) {
            u64 zi[RPG], zf[RPG], zg[RPG], zo[RPG];
#pragma unroll
            for (int r = 0; r < RPG; r++) { zi[r]=0; zf[r]=0; zg[r]=0; zo[r]=0; }
            accX (zi, zf, zg, zo, sm + W0XA_OFF, sm + W0XB_OFF, XSg, u);
            acc25(zi, zf, zg, zo, sm + W0HA_OFF, sm + W0HB_OFF, HS0, u);
#pragma unroll
            for (int r = 0; r < RPG; r++) {
                float a, b;
                unpack2(zi[r], a, b); const float si = a + b + bi0;
                unpack2(zf[r], a, b); const float sf = a + b + bf0;
                unpack2(zg[r], a, b); const float sg = a + b + bg0;
                unpack2(zo[r], a, b); const float so = a + b + bo0;
                const float ig = sigmoidf_(si);
                const float fg = sigmoidf_(sf);
                const float gg = tanhf_(sg);
                const float og = sigmoidf_(so);
                c0[r] = fg * c0[r] + ig * gg;
                hn[r] = og * tanhf_(c0[r]);
            }
        }
        barg(bid);
        if (act) {
#pragma unroll
            for (int r = 0; r < RPG; r++) HS0[r*HPAD + u] = hn[r];
        }
        barg(bid);

        // ================= layer 1 =================
        if (act) {
            u64 zi[RPG], zf[RPG], zg[RPG], zo[RPG];
#pragma unroll
            for (int r = 0; r < RPG; r++) { zi[r]=0; zf[r]=0; zg[r]=0; zo[r]=0; }
            acc25(zi, zf, zg, zo, sm + W1IA_OFF, sm + W1IB_OFF, HS0, u);
            acc25(zi, zf, zg, zo, sm + W1RA_OFF, sm + W1RB_OFF, HS1, u);
#pragma unroll
            for (int r = 0; r < RPG; r++) {
                float a, b;
                unpack2(zi[r], a, b); const float si = a + b + bi1;
                unpack2(zf[r], a, b); const float sf = a + b + bf1;
                unpack2(zg[r], a, b); const float sg = a + b + bg1;
                unpack2(zo[r], a, b); const float so = a + b + bo1;
                const float ig = sigmoidf_(si);
                const float fg = sigmoidf_(sf);
                const float gg = tanhf_(sg);
                const float og = sigmoidf_(so);
                c1[r] = fg * c1[r] + ig * gg;
                hn[r] = og * tanhf_(c1[r]);
            }
        }
        barg(bid);
        if (act) {
#pragma unroll
            for (int r = 0; r < RPG; r++) HS1[r*HPAD + u] = hn[r];
        }
        barg(bid);

        // ================= layer 2 =================
        if (act) {
            u64 zi[RPG], zf[RPG], zg[RPG], zo[RPG];
#pragma unroll
            for (int r = 0; r < RPG; r++) { zi[r]=0; zf[r]=0; zg[r]=0; zo[r]=0; }
            acc25(zi, zf, zg, zo, sm + W2IA_OFF, sm + W2IB_OFF, HS1, u);
            acc25(zi, zf, zg, zo, sm + W2RA_OFF, sm + W2RB_OFF, HS2, u);
#pragma unroll
            for (int r = 0; r < RPG; r++) {
                float a, b;
                unpack2(zi[r], a, b); const float si = a + b + bi2;
                unpack2(zf[r], a, b); const float sf = a + b + bf2;
                unpack2(zg[r], a, b); const float sg = a + b + bg2;
                unpack2(zo[r], a, b); const float so = a + b + bo2;
                const float ig = sigmoidf_(si);
                const float fg = sigmoidf_(sf);
                const float gg = tanhf_(sg);
                const float og = sigmoidf_(so);
                c2[r] = fg * c2[r] + ig * gg;
                hn[r] = og * tanhf_(c2[r]);
            }
        }
        barg(bid);
        if (act) {
#pragma unroll
            for (int r = 0; r < RPG; r++) HS2[r*HPAD + u] = hn[r];
        }
        barg(bid);
    }

    __syncthreads();

    // ---- final linear: out[b] = h2[b] . Wlin + blin ----
    if (tid < BC) {
        float s = blin[0];
#pragma unroll 10
        for (int uu = 0; uu < Hn; uu++)
            s += HS[2*(BC*HPAD) + tid*HPAD + uu] * Wlin[uu];
        out[bbase + tid] = s;
    }
}

extern "C" void kernel_launch(void* const* d_in, const int* in_sizes, int n_in,
                              void* d_out, int out_size)
{
    (void)in_sizes; (void)n_in; (void)out_size;
    const float* x    = (const float*)d_in[0];
    const float* Wih0 = (const float*)d_in[1];
    const float* Whh0 = (const float*)d_in[2];
    const float* bih0 = (const float*)d_in[3];
    const float* bhh0 = (const float*)d_in[4];
    const float* Wih1 = (const float*)d_in[5];
    const float* Whh1 = (const float*)d_in[6];
    const float* bih1 = (const float*)d_in[7];
    const float* bhh1 = (const float*)d_in[8];
    const float* Wih2 = (const float*)d_in[9];
    const float* Whh2 = (const float*)d_in[10];
    const float* bih2 = (const float*)d_in[11];
    const float* bhh2 = (const float*)d_in[12];
    const float* Wlin = (const float*)d_in[13];
    const float* blin = (const float*)d_in[14];
    float* out = (float*)d_out;

    cudaFuncSetAttribute(lstm_fused, cudaFuncAttributeMaxDynamicSharedMemorySize, SMEM_BYTES);
    lstm_fused<<<Bn / BC, NTHREADS, SMEM_BYTES>>>(
        x, Wih0, Whh0, bih0, bhh0,
        Wih1, Whh1, bih1, bhh1,
        Wih2, Whh2, bih2, bhh2,
        Wlin, blin, out);
}